// round 10
// baseline (speedup 1.0000x reference)
#include <cuda_runtime.h>
#include <cstdint>

#define D 256
#define RT 8        // relations per block in k_rel
#define KT3 16      // k-tile floats per half per stage
#define PAD3 20     // smem row stride (floats): quad-stride 5 -> conflict-free LDS.128
#define HBUF (768 * PAD3)

typedef unsigned long long u64;

// Scratch (no cudaMalloc allowed).
__device__ float g_sub[D];
__device__ float g_pA[3 * D];
__device__ float g_pB[3 * D];
__device__ float g_gi[3 * D];
__device__ float g_obj[2048 * D];   // supports up to R=2048 (problem has R=1000)
__device__ int g_c1, g_c2;          // prolog spin-barrier counters (reset by k_rel)

__device__ __forceinline__ float sigmoidf_(float x) { return 1.0f / (1.0f + expf(-x)); }

__device__ __forceinline__ float wredsum(float v) {
#pragma unroll
    for (int o = 16; o; o >>= 1) v += __shfl_xor_sync(0xffffffffu, v, o);
    return v;
}

__device__ __forceinline__ void fma2(u64& acc, u64 a, u64 b) {
    asm("fma.rn.f32x2 %0, %1, %2, %3;" : "=l"(acc) : "l"(a), "l"(b), "l"(acc));
}
__device__ __forceinline__ float unpack_sum(u64 acc) {
    float lo = __uint_as_float((unsigned)(acc & 0xffffffffu));
    float hi = __uint_as_float((unsigned)(acc >> 32));
    return lo + hi;
}

// Grid-wide spin barrier (96 co-resident blocks; counters reset by k_rel).
__device__ __forceinline__ void gbar(int* c, int n) {
    __threadfence();
    __syncthreads();
    if (threadIdx.x == 0) {
        atomicAdd(c, 1);
        while (atomicAdd(c, 0) < n) { }
    }
    __syncthreads();
}

__device__ __forceinline__ float warp_dot256(const float* __restrict__ Wrow,
                                             const float* x, int lane) {
    const float4* w4 = reinterpret_cast<const float4*>(Wrow);
    const float4* x4 = reinterpret_cast<const float4*>(x);
    float4 a0 = w4[lane],      b0 = x4[lane];
    float4 a1 = w4[lane + 32], b1 = x4[lane + 32];
    float s = a0.x * b0.x + a0.y * b0.y + a0.z * b0.z + a0.w * b0.w
            + a1.x * b1.x + a1.y * b1.y + a1.z * b1.z + a1.w * b1.w;
    return wredsum(s);
}

__device__ __forceinline__ float warp_dot256_cg(const float* __restrict__ Wrow,
                                                const float* x, int lane) {
    const float4* w4 = reinterpret_cast<const float4*>(Wrow);
    const float4* x4 = reinterpret_cast<const float4*>(x);
    float4 a0 = w4[lane],      b0 = __ldcg(&x4[lane]);
    float4 a1 = w4[lane + 32], b1 = __ldcg(&x4[lane + 32]);
    float s = a0.x * b0.x + a0.y * b0.y + a0.z * b0.z + a0.w * b0.w
            + a1.x * b1.x + a1.y * b1.y + a1.z * b1.z + a1.w * b1.w;
    return wredsum(s);
}

// ---------------------------------------------------------------------------
// Fused prolog (96 blocks x 256 threads). gi dot hoisted ABOVE barrier 1 so it
// overlaps phase A. Then gh (needs sub) | barrier | r0 combine | g_gi.
// ---------------------------------------------------------------------------
__global__ void k_prolog(const float* __restrict__ enc, const float* __restrict__ mask,
                         const float* __restrict__ W_ih, const float* __restrict__ W_hh,
                         const float* __restrict__ b_ih, const float* __restrict__ b_hh,
                         const float* __restrict__ sub_W, const float* __restrict__ sub_b) {
    __shared__ float s_r0[D];
    int t = threadIdx.x;
    int lane = t & 31;
    int row = blockIdx.x * 8 + (t >> 5);   // 0..767

    // gi partial (no dependency on sub) — overlaps phase A
    float gi = warp_dot256(W_ih + (size_t)row * D, enc, lane);

    // Phase A (blocks 0..31 -> output dim j = row in 0..255)
    if (blockIdx.x < 32) {
        float s = warp_dot256(sub_W + (size_t)row * D, mask, lane);
        if (lane == 0) g_sub[row] = tanhf(s + sub_b[row]);
    }
    gbar(&g_c1, 96);

    // Phase B: gh (needs sub)
    {
        float gh = warp_dot256_cg(W_hh + (size_t)row * D, g_sub, lane);
        if (lane == 0) {
            g_pA[row] = gi + b_ih[row];
            g_pB[row] = gh + b_hh[row];
        }
    }
    gbar(&g_c2, 96);

    // r0 combine (redundant per block, into smem)
    {
        float ar = __ldcg(&g_pA[t])        , hr = __ldcg(&g_pB[t]);
        float az = __ldcg(&g_pA[D + t])    , hz = __ldcg(&g_pB[D + t]);
        float an = __ldcg(&g_pA[2 * D + t]), hn = __ldcg(&g_pB[2 * D + t]);
        float sub = __ldcg(&g_sub[t]);
        float rg = sigmoidf_(ar + hr);
        float zg = sigmoidf_(az + hz);
        float ng = tanhf(an + rg * hn);
        s_r0[t] = (1.0f - zg) * ng + zg * sub;
    }
    __syncthreads();

    // Phase C: g_gi = W_ih @ r0 + b_ih
    {
        float s = warp_dot256(W_ih + (size_t)row * D, s_r0, lane);
        if (lane == 0) g_gi[row] = s + b_ih[row];
    }
}

// ---------------------------------------------------------------------------
// k_rel v9: 512 threads, split-K with R3's exact register tile.
// Half kh = t>>8 owns k-range [kh*128, kh*128+128); thread tt = t&255 owns
// gate rows (tt, tt+256, tt+512) x 8 relations (48 fma2 : 11 LDS, R3 ratio).
// KT3=16 tiles, LDG->STS staging (PAD3=20: conflict-free LDS, 2-way STS).
// Half 1's partials merge through smem; half 0 combines + stores.
// ---------------------------------------------------------------------------
__global__ void __launch_bounds__(512, 1)
k_rel(const float* __restrict__ rel_table, const float* __restrict__ W_hh,
      const float* __restrict__ b_hh, const float* __restrict__ obj_W,
      const float* __restrict__ obj_b, int R) {
    extern __shared__ float sm[];
    float* s_h    = sm + 2 * HBUF;          // RT * D
    float* s_rj   = s_h + RT * D;           // RT * D
    float* s_part = s_rj + RT * D;          // 768 * 8 (gate partials; reused for obj)

    if (blockIdx.x == 0 && threadIdx.x == 0) { g_c1 = 0; g_c2 = 0; }

    int t  = threadIdx.x;
    int kh = t >> 8;
    int tt = t & 255;
    int K0 = kh * 128;
    int rbase = blockIdx.x * RT;
    float* myb = sm + kh * HBUF;

    // stage h vectors (coalesced)
    for (int idx = t; idx < RT * D; idx += 512) {
        int r = idx >> 8;
        s_h[idx] = (rbase + r < R) ? rel_table[(size_t)(rbase + r) * D + (idx & 255)] : 0.0f;
    }

    u64 aR[RT], aZ[RT], aN[RT];
#pragma unroll
    for (int r = 0; r < RT; r++) { aR[r] = 0; aZ[r] = 0; aN[r] = 0; }

    // ---- gate phase: 8 tiles of KT3=16 per half ----
    for (int tile = 0; tile < 128 / KT3; tile++) {
        int kbase = K0 + tile * KT3;
        __syncthreads();
        // stage 768 rows x 16 cols of this half's W_hh slice (12 float4/thread)
#pragma unroll
        for (int j = 0; j < 12; j++) {
            int qid = j * 256 + tt;          // 0..3071
            int row = qid >> 2;              // 0..767
            int kq  = qid & 3;
            *reinterpret_cast<float4*>(&myb[row * PAD3 + kq * 4]) =
                *reinterpret_cast<const float4*>(&W_hh[(size_t)row * D + kbase + kq * 4]);
        }
        __syncthreads();
#pragma unroll
        for (int kk = 0; kk < KT3; kk += 4) {
            int kg = kbase + kk;
            ulonglong2 wr = *reinterpret_cast<const ulonglong2*>(&myb[(0 * 256 + tt) * PAD3 + kk]);
            ulonglong2 wz = *reinterpret_cast<const ulonglong2*>(&myb[(1 * 256 + tt) * PAD3 + kk]);
            ulonglong2 wn = *reinterpret_cast<const ulonglong2*>(&myb[(2 * 256 + tt) * PAD3 + kk]);
#pragma unroll
            for (int r = 0; r < RT; r++) {
                ulonglong2 h2 = *reinterpret_cast<const ulonglong2*>(&s_h[r * D + kg]);
                fma2(aR[r], wr.x, h2.x); fma2(aR[r], wr.y, h2.y);
                fma2(aZ[r], wz.x, h2.x); fma2(aZ[r], wz.y, h2.y);
                fma2(aN[r], wn.x, h2.x); fma2(aN[r], wn.y, h2.y);
            }
        }
    }
    __syncthreads();
    if (kh == 1) {
#pragma unroll
        for (int r = 0; r < RT; r++) {
            s_part[(0 * 256 + tt) * 8 + r] = unpack_sum(aR[r]);
            s_part[(1 * 256 + tt) * 8 + r] = unpack_sum(aZ[r]);
            s_part[(2 * 256 + tt) * 8 + r] = unpack_sum(aN[r]);
        }
    }
    __syncthreads();

    // ---- GRU combine (half 0) -> s_rj ----
    if (kh == 0) {
        float ir = g_gi[tt], iz = g_gi[D + tt], in_ = g_gi[2 * D + tt];
        float bhr = b_hh[tt], bhz = b_hh[D + tt], bhn = b_hh[2 * D + tt];
#pragma unroll
        for (int r = 0; r < RT; r++) {
            float AR = unpack_sum(aR[r]) + s_part[(0 * 256 + tt) * 8 + r];
            float AZ = unpack_sum(aZ[r]) + s_part[(1 * 256 + tt) * 8 + r];
            float AN = unpack_sum(aN[r]) + s_part[(2 * 256 + tt) * 8 + r];
            float rg = sigmoidf_(ir + AR + bhr);
            float zg = sigmoidf_(iz + AZ + bhz);
            float ng = tanhf(in_ + rg * (AN + bhn));
            s_rj[r * D + tt] = (1.0f - zg) * ng + zg * s_h[r * D + tt];
        }
    }
    __syncthreads();

    // ---- obj phase: split-K, 8 tiles per half ----
    u64 aO[RT];
#pragma unroll
    for (int r = 0; r < RT; r++) aO[r] = 0;

    for (int tile = 0; tile < 128 / KT3; tile++) {
        int kbase = K0 + tile * KT3;
        __syncthreads();
        // stage 256 rows x 16 cols of obj_W slice (4 float4/thread)
#pragma unroll
        for (int j = 0; j < 4; j++) {
            int qid = j * 256 + tt;          // 0..1023
            int row = qid >> 2;              // 0..255
            int kq  = qid & 3;
            *reinterpret_cast<float4*>(&myb[row * PAD3 + kq * 4]) =
                *reinterpret_cast<const float4*>(&obj_W[(size_t)row * D + kbase + kq * 4]);
        }
        __syncthreads();
#pragma unroll
        for (int kk = 0; kk < KT3; kk += 4) {
            int kg = kbase + kk;
            ulonglong2 wo = *reinterpret_cast<const ulonglong2*>(&myb[tt * PAD3 + kk]);
#pragma unroll
            for (int r = 0; r < RT; r++) {
                ulonglong2 h2 = *reinterpret_cast<const ulonglong2*>(&s_rj[r * D + kg]);
                fma2(aO[r], wo.x, h2.x); fma2(aO[r], wo.y, h2.y);
            }
        }
    }
    __syncthreads();
    if (kh == 1) {
#pragma unroll
        for (int r = 0; r < RT; r++) s_part[tt * 8 + r] = unpack_sum(aO[r]);
    }
    __syncthreads();
    if (kh == 0) {
        float ob = obj_b[tt];
#pragma unroll
        for (int r = 0; r < RT; r++) {
            if (rbase + r < R)
                g_obj[(size_t)(rbase + r) * D + tt] =
                    tanhf(unpack_sum(aO[r]) + s_part[tt * 8 + r] + ob);
        }
    }
}

#define REL_SMEM ((2 * HBUF + 2 * RT * D + 768 * 8) * 4)

// ---------------------------------------------------------------------------
// Single-pass scatter, 8 rows/warp for MLP=16 (+ seed row in block 0;
// seed==E never collides with tail_ids==0..E-1). __stcs streaming stores.
// ---------------------------------------------------------------------------
__global__ void k_scatter(const float* __restrict__ ent_table, const int* __restrict__ rel_ids,
                          const int* __restrict__ tail_ids, const int* __restrict__ tails_state,
                          const int* __restrict__ origin_ids, const int* __restrict__ seed_p,
                          float* __restrict__ out, int E) {
    if (blockIdx.x == 0) {
        int seed = *seed_p;
        out[(size_t)seed * D + threadIdx.x] = g_sub[threadIdx.x];
    }

    int warp = threadIdx.x >> 5;
    int lane = threadIdx.x & 31;
    int base = (blockIdx.x * 8 + warp) * 8;

    float4 v[8][2];
    float4* dst[8];
    bool ok[8];
#pragma unroll
    for (int i = 0; i < 8; i++) {
        int row = base + i;
        ok[i] = row < E;
        if (ok[i]) {
            int st = tails_state[row];
            const float4* src = (st == 1)
                ? reinterpret_cast<const float4*>(ent_table) + (size_t)origin_ids[row] * (D / 4)
                : reinterpret_cast<const float4*>(g_obj) + (size_t)rel_ids[row] * (D / 4);
            dst[i] = reinterpret_cast<float4*>(out) + (size_t)tail_ids[row] * (D / 4);
            v[i][0] = src[lane];
            v[i][1] = src[lane + 32];
        }
    }
#pragma unroll
    for (int i = 0; i < 8; i++) {
        if (ok[i]) {
            __stcs(&dst[i][lane], v[i][0]);
            __stcs(&dst[i][lane + 32], v[i][1]);
        }
    }
}

// ---------------------------------------------------------------------------
extern "C" void kernel_launch(void* const* d_in, const int* in_sizes, int n_in,
                              void* d_out, int out_size) {
    const float* enc       = (const float*)d_in[0];
    const float* mask      = (const float*)d_in[1];
    const float* ent_table = (const float*)d_in[2];
    const float* rel_table = (const float*)d_in[3];
    const float* W_ih      = (const float*)d_in[4];
    const float* W_hh      = (const float*)d_in[5];
    const float* b_ih      = (const float*)d_in[6];
    const float* b_hh      = (const float*)d_in[7];
    const float* sub_W     = (const float*)d_in[8];
    const float* sub_b     = (const float*)d_in[9];
    const float* obj_W     = (const float*)d_in[10];
    const float* obj_b     = (const float*)d_in[11];
    const int*   rel_ids   = (const int*)d_in[12];
    const int*   tail_ids  = (const int*)d_in[13];
    const int*   tails_st  = (const int*)d_in[14];
    const int*   origin    = (const int*)d_in[15];
    const int*   seed_p    = (const int*)d_in[16];
    float* out = (float*)d_out;

    int E = in_sizes[12];
    int R = in_sizes[3] / D;

    static bool init = false;
    if (!init) {
        cudaFuncSetAttribute(k_rel, cudaFuncAttributeMaxDynamicSharedMemorySize, REL_SMEM);
        init = true;
    }

    k_prolog<<<96, 256>>>(enc, mask, W_ih, W_hh, b_ih, b_hh, sub_W, sub_b);
    k_rel<<<(R + RT - 1) / RT, 512, REL_SMEM>>>(rel_table, W_hh, b_hh, obj_W, obj_b, R);
    k_scatter<<<(E + 63) / 64, 256>>>(ent_table, rel_ids, tail_ids, tails_st, origin,
                                      seed_p, out, E);
}